// round 13
// baseline (speedup 1.0000x reference)
#include <cuda_runtime.h>
#include <math.h>

#define HIDDEN 1024
#define HEADS  8
#define HEAD   128
#define BATCH  512

__device__ __forceinline__ float dot4(float4 a, float4 b) {
    return a.x*b.x + a.y*b.y + a.z*b.z + a.w*b.w;
}

// 16-byte async copy to shared (L2-only): register-free prefetch.
__device__ __forceinline__ void cp_async16(void* dst_smem, const float* src) {
    unsigned int d = (unsigned int)__cvta_generic_to_shared(dst_smem);
    asm volatile("cp.async.cg.shared.global [%0], [%1], 16;" :: "r"(d), "l"(src));
}

// ---------------------------------------------------------------------------
// Fully fused gate GEMV + mLSTM step + GroupNorm.
// One (b,h) tile per block, 128 threads, 8 CTAs/SM.
// Same proven stream as rounds 4/12 (entry prefetch + rolling depth-8 ring,
// .cs loads/stores, 32 warps/SM, identical aggregate in-flight bytes) but
// HALF-SIZE CTAs: barriers span 4 warps instead of 8, and 8 independently
// phased CTAs per SM interleave their prologue/epilogue serial phases ->
// finer-grained filling of the phase-locked DRAM idle windows.
// Gate GEMV split into two sequential halves to keep peak regs <= 64.
// ---------------------------------------------------------------------------
__global__ __launch_bounds__(128, 8) void mlstm_fused_kernel(
    const float* __restrict__ q, const float* __restrict__ k,
    const float* __restrict__ v, const float* __restrict__ cell,
    const float* __restrict__ norm, const float* __restrict__ maxs,
    const float* __restrict__ Wi, const float* __restrict__ bi,
    const float* __restrict__ Wf, const float* __restrict__ bf,
    const float* __restrict__ gamma, const float* __restrict__ beta,
    float* __restrict__ out, float* __restrict__ cell_out,
    float* __restrict__ norm_out, float* __restrict__ max_out)
{
    int bh   = blockIdx.x;
    int b    = bh >> 3;
    int h    = bh & 7;
    int tid  = threadIdx.x;          // 0..127
    int lane = tid & 31;
    int warp = tid >> 5;             // 0..3

    __shared__ __align__(16) float q_s[HEAD];
    __shared__ __align__(16) float k_s[HEAD];
    __shared__ __align__(16) float v_s[HEAD];
    __shared__ __align__(16) float norm_s[HEAD];
    __shared__ __align__(16) float4 snum[128];
    __shared__ float pig[4], pfg[4], pq[4];
    __shared__ float s_mu, s_rstd;

    const float rsqrtD = 0.08838834764831845f;  // 1/sqrt(128)

    // ---- cell tile: warp = row-group (4 rows/iter), lane = float4 column ---
    const float4* cp = (const float4*)(cell + (size_t)bh * HEAD * HEAD)
                       + warp * 32 + lane;
    float4* op = cell_out
               ? (float4*)(cell_out + (size_t)bh * HEAD * HEAD) + warp * 32 + lane
               : (float4*)0;

    // ---- entry prefetches (independent of the gate GEMV) -------------------
    float4 cv[8];
    #pragma unroll
    for (int i = 0; i < 8; ++i)
        cv[i] = __ldcs(cp + i * 128);           // rows warp, warp+4, ..., warp+28

    if (tid < 32) {       // norm row -> smem, register-free
        cp_async16(&norm_s[tid * 4], norm + (size_t)bh * HEAD + tid * 4);
        asm volatile("cp.async.commit_group;" ::: "memory");
    }
    float m_old = maxs[bh];
    float bih   = bi[h];
    float bfh   = bf[h];

    // ---- gate pre-activations in two sequential halves (reg pressure) ------
    const float4* qrow = (const float4*)(q + (size_t)b * HIDDEN);
    const float4* krow = (const float4*)(k + (size_t)b * HIDDEN);
    const float4* vrow = (const float4*)(v + (size_t)b * HIDDEN);
    const float4* Wi4  = (const float4*)Wi + (size_t)h * 768;
    const float4* Wf4  = (const float4*)Wf + (size_t)h * 768;

    float ai = 0.f, af = 0.f;
    {   // half 0: qkv float4 indices [0,128)
        float4 xq = qrow[tid];
        float4 xk = krow[tid];
        float4 xv = vrow[tid];
        ai += dot4(xq, Wi4[tid]) + dot4(xk, Wi4[256 + tid]) + dot4(xv, Wi4[512 + tid]);
        af += dot4(xq, Wf4[tid]) + dot4(xk, Wf4[256 + tid]) + dot4(xv, Wf4[512 + tid]);
        if (h < 4 && warp == h) {     // head f4 slice [h*32, h*32+32) lives here
            ((float4*)q_s)[lane] = xq;
            float4 sk;
            sk.x = xk.x * rsqrtD; sk.y = xk.y * rsqrtD;
            sk.z = xk.z * rsqrtD; sk.w = xk.w * rsqrtD;
            ((float4*)k_s)[lane] = sk;
            ((float4*)v_s)[lane] = xv;
        }
    }
    {   // half 1: qkv float4 indices [128,256)
        float4 xq = qrow[tid + 128];
        float4 xk = krow[tid + 128];
        float4 xv = vrow[tid + 128];
        ai += dot4(xq, Wi4[128 + tid]) + dot4(xk, Wi4[384 + tid]) + dot4(xv, Wi4[640 + tid]);
        af += dot4(xq, Wf4[128 + tid]) + dot4(xk, Wf4[384 + tid]) + dot4(xv, Wf4[640 + tid]);
        if (h >= 4 && warp == h - 4) {  // head f4 slice lives in this half
            ((float4*)q_s)[lane] = xq;
            float4 sk;
            sk.x = xk.x * rsqrtD; sk.y = xk.y * rsqrtD;
            sk.z = xk.z * rsqrtD; sk.w = xk.w * rsqrtD;
            ((float4*)k_s)[lane] = sk;
            ((float4*)v_s)[lane] = xv;
        }
    }

    #pragma unroll
    for (int off = 16; off > 0; off >>= 1) {
        ai += __shfl_xor_sync(0xffffffffu, ai, off);
        af += __shfl_xor_sync(0xffffffffu, af, off);
    }
    if (lane == 0) { pig[warp] = ai; pfg[warp] = af; }
    if (tid < 32)
        asm volatile("cp.async.wait_group 0;" ::: "memory");
    __syncthreads();                                   // sync #1

    float igp = bih + pig[0] + pig[1] + pig[2] + pig[3];
    float fgp = bfh + pfg[0] + pfg[1] + pfg[2] + pfg[3];

    float log_f = fminf(fgp, 0.f) - log1pf(expf(-fabsf(fgp)));   // log sigmoid
    float m_new = fmaxf(igp, m_old + log_f);
    float i_g   = expf(igp - m_new);
    float f_g   = expf(log_f + m_old - m_new);

    if (tid == 0 && max_out) max_out[bh] = m_new;

    // ---- norm update + qn partials ------------------------------------------
    {
        float nn = fmaf(f_g, norm_s[tid], i_g * k_s[tid]);
        if (norm_out) norm_out[(size_t)bh * HEAD + tid] = nn;
        float qn = q_s[tid] * nn;
        #pragma unroll
        for (int off = 16; off > 0; off >>= 1)
            qn += __shfl_xor_sync(0xffffffffu, qn, off);
        if (lane == 0) pq[warp] = qn;
    }

    // ---- main stream: 32 iterations of 4 rows, rolling depth-8 ring ---------
    float4 vreg = ((const float4*)v_s)[lane];
    float4 num  = make_float4(0.f, 0.f, 0.f, 0.f);

    #pragma unroll
    for (int i = 0; i < 32; ++i) {
        float4 c = cv[i & 7];
        if (i + 8 < 32)
            cv[i & 7] = __ldcs(cp + (i + 8) * 128);   // keep 8 rows in flight
        int r = i * 4 + warp;
        float a = i_g * k_s[r];
        float4 cn;
        cn.x = fmaf(f_g, c.x, a * vreg.x);
        cn.y = fmaf(f_g, c.y, a * vreg.y);
        cn.z = fmaf(f_g, c.z, a * vreg.z);
        cn.w = fmaf(f_g, c.w, a * vreg.w);
        if (op) __stcs(op + i * 128, cn);
        float qr = q_s[r];
        num.x = fmaf(qr, cn.x, num.x);
        num.y = fmaf(qr, cn.y, num.y);
        num.z = fmaf(qr, cn.z, num.z);
        num.w = fmaf(qr, cn.w, num.w);
    }

    // ---- numerator reduction + denominator + GN stats in warp 0 -------------
    snum[tid] = num;
    __syncthreads();                                   // sync #2 (covers pq)
    if (tid < 32) {
        float4 a  = snum[tid];
        float4 b1 = snum[tid + 32];
        float4 b2 = snum[tid + 64];
        float4 b3 = snum[tid + 96];
        a.x += b1.x + b2.x + b3.x;
        a.y += b1.y + b2.y + b3.y;
        a.z += b1.z + b2.z + b3.z;
        a.w += b1.w + b2.w + b3.w;
        float qn    = pq[0] + pq[1] + pq[2] + pq[3];
        float denom = fmaxf(fabsf(qn), expf(-m_new)) + 1e-6f;
        float inv   = 1.f / denom;
        a.x *= inv; a.y *= inv; a.z *= inv; a.w *= inv;
        snum[tid] = a;                 // flattened: o[0..127]
        float so  = a.x + a.y + a.z + a.w;
        float so2 = a.x*a.x + a.y*a.y + a.z*a.z + a.w*a.w;
        #pragma unroll
        for (int off = 16; off > 0; off >>= 1) {
            so  += __shfl_xor_sync(0xffffffffu, so,  off);
            so2 += __shfl_xor_sync(0xffffffffu, so2, off);
        }
        if (lane == 0) {
            float mu  = so * (1.f / HEAD);
            float var = so2 * (1.f / HEAD) - mu * mu;
            s_mu   = mu;
            s_rstd = rsqrtf(var + 1e-5f);
        }
    }
    __syncthreads();                                   // sync #3

    {
        float o  = ((const float*)snum)[tid];
        int   ch = h * HEAD + tid;
        out[(size_t)b * HIDDEN + ch] = (o - s_mu) * s_rstd * gamma[ch] + beta[ch];
    }
}

// ---------------------------------------------------------------------------
extern "C" void kernel_launch(void* const* d_in, const int* in_sizes, int n_in,
                              void* d_out, int out_size)
{
    const float* q     = (const float*)d_in[0];
    const float* k     = (const float*)d_in[1];
    const float* v     = (const float*)d_in[2];
    const float* cell  = (const float*)d_in[3];
    const float* norm  = (const float*)d_in[4];
    const float* maxs  = (const float*)d_in[5];
    const float* Wi    = (const float*)d_in[6];
    const float* bi    = (const float*)d_in[7];
    const float* Wf    = (const float*)d_in[8];
    const float* bf    = (const float*)d_in[9];
    const float* gamma = (const float*)d_in[10];
    const float* beta  = (const float*)d_in[11];

    float* out = (float*)d_out;

    const size_t OUT_N  = (size_t)BATCH * HIDDEN;                 // 524288
    const size_t CELL_N = (size_t)BATCH * HEADS * HEAD * HEAD;    // 67108864
    const size_t NORM_N = (size_t)BATCH * HEADS * HEAD;           // 524288
    const size_t MAX_N  = (size_t)BATCH * HEADS;                  // 4096

    float* cell_out = 0;
    float* norm_out = 0;
    float* max_out  = 0;
    if ((size_t)out_size >= OUT_N + CELL_N + NORM_N + MAX_N) {
        cell_out = out + OUT_N;
        norm_out = cell_out + CELL_N;
        max_out  = norm_out + NORM_N;
    }

    mlstm_fused_kernel<<<BATCH * HEADS, 128>>>(q, k, v, cell, norm, maxs,
                                               Wi, bi, Wf, bf, gamma, beta,
                                               out, cell_out, norm_out, max_out);
}

// round 14
// speedup vs baseline: 1.0318x; 1.0318x over previous
#include <cuda_runtime.h>
#include <math.h>

#define HIDDEN 1024
#define HEADS  8
#define HEAD   128
#define BATCH  512

__device__ __forceinline__ float dot4(float4 a, float4 b) {
    return a.x*b.x + a.y*b.y + a.z*b.z + a.w*b.w;
}

// 16-byte async copy to shared (L2-only): register-free prefetch.
__device__ __forceinline__ void cp_async16(void* dst_smem, const float* src) {
    unsigned int d = (unsigned int)__cvta_generic_to_shared(dst_smem);
    asm volatile("cp.async.cg.shared.global [%0], [%1], 16;" :: "r"(d), "l"(src));
}

// ---------------------------------------------------------------------------
// Fully fused gate GEMV + mLSTM step + GroupNorm. One (b,h) tile per block,
// 256 threads, 4 CTAs/SM. FINAL (round-12 structure, best of 8 variants):
//   - first 8 cell-row loads issued at kernel ENTRY, hiding the gate GEMV
//   - rolling depth-8 register ring -> constant MLP=8 per warp
//   - norm row prefetched via cp.async at entry; maxs/bi/bf hoisted to entry
//   - compressed epilogue: 32-thread reducer applies denominator + GN stats
// Measured: 78.5us kernel, 79.3% DRAM (~6.28 TB/s) -- the HW ceiling for
// this 50/50 read+write streaming pattern; compulsory traffic is 537MB.
// ---------------------------------------------------------------------------
__global__ __launch_bounds__(256, 4) void mlstm_fused_kernel(
    const float* __restrict__ q, const float* __restrict__ k,
    const float* __restrict__ v, const float* __restrict__ cell,
    const float* __restrict__ norm, const float* __restrict__ maxs,
    const float* __restrict__ Wi, const float* __restrict__ bi,
    const float* __restrict__ Wf, const float* __restrict__ bf,
    const float* __restrict__ gamma, const float* __restrict__ beta,
    float* __restrict__ out, float* __restrict__ cell_out,
    float* __restrict__ norm_out, float* __restrict__ max_out)
{
    int bh   = blockIdx.x;
    int b    = bh >> 3;
    int h    = bh & 7;
    int tid  = threadIdx.x;
    int lane = tid & 31;
    int warp = tid >> 5;

    __shared__ __align__(16) float q_s[HEAD];
    __shared__ __align__(16) float k_s[HEAD];
    __shared__ __align__(16) float v_s[HEAD];
    __shared__ __align__(16) float norm_s[HEAD];
    __shared__ float4 snum[256];
    __shared__ float pig[8], pfg[8], pq[4];
    __shared__ float s_mu, s_rstd;

    const float rsqrtD = 0.08838834764831845f;  // 1/sqrt(128)

    // ---- cell tile pointers: warp = row-group, lane = float4 column --------
    const float4* cp = (const float4*)(cell + (size_t)bh * HEAD * HEAD)
                       + warp * 32 + lane;
    float4* op = cell_out
               ? (float4*)(cell_out + (size_t)bh * HEAD * HEAD) + warp * 32 + lane
               : (float4*)0;

    // ---- entry prefetches (all independent of the gate GEMV) ---------------
    float4 cv[8];
    #pragma unroll
    for (int i = 0; i < 8; ++i)
        cv[i] = __ldcs(cp + i * 256);

    if (tid < 32) {       // norm row -> smem, register-free
        cp_async16(&norm_s[tid * 4], norm + (size_t)bh * HEAD + tid * 4);
        asm volatile("cp.async.commit_group;" ::: "memory");
    }
    float m_old = maxs[bh];                      // block-uniform scalars
    float bih   = bi[h];
    float bfh   = bf[h];

    // ---- gate pre-activations: igp/fgp = qkv_row . W[h] + b[h] -------------
    const float4* qrow = (const float4*)(q + (size_t)b * HIDDEN);
    const float4* krow = (const float4*)(k + (size_t)b * HIDDEN);
    const float4* vrow = (const float4*)(v + (size_t)b * HIDDEN);
    const float4* Wi4  = (const float4*)Wi + (size_t)h * 768;
    const float4* Wf4  = (const float4*)Wf + (size_t)h * 768;

    float4 xq = qrow[tid];
    float4 xk = krow[tid];
    float4 xv = vrow[tid];

    float ai = dot4(xq, Wi4[tid]) + dot4(xk, Wi4[256 + tid]) + dot4(xv, Wi4[512 + tid]);
    float af = dot4(xq, Wf4[tid]) + dot4(xk, Wf4[256 + tid]) + dot4(xv, Wf4[512 + tid]);

    // warp h already holds the head slice in registers -> stash to smem
    if (warp == h) {
        ((float4*)q_s)[lane] = xq;
        float4 sk;
        sk.x = xk.x * rsqrtD; sk.y = xk.y * rsqrtD;
        sk.z = xk.z * rsqrtD; sk.w = xk.w * rsqrtD;
        ((float4*)k_s)[lane] = sk;
        ((float4*)v_s)[lane] = xv;
    }

    #pragma unroll
    for (int off = 16; off > 0; off >>= 1) {
        ai += __shfl_xor_sync(0xffffffffu, ai, off);
        af += __shfl_xor_sync(0xffffffffu, af, off);
    }
    if (lane == 0) { pig[warp] = ai; pfg[warp] = af; }
    if (tid < 32)   // norm row must be in smem before sync publishes it
        asm volatile("cp.async.wait_group 0;" ::: "memory");
    __syncthreads();                                   // sync #1

    float igp = bih, fgp = bfh;
    #pragma unroll
    for (int w = 0; w < 8; ++w) { igp += pig[w]; fgp += pfg[w]; }

    float log_f = fminf(fgp, 0.f) - log1pf(expf(-fabsf(fgp)));   // log sigmoid
    float m_new = fmaxf(igp, m_old + log_f);
    float i_g   = expf(igp - m_new);
    float f_g   = expf(log_f + m_old - m_new);

    if (tid == 0 && max_out) max_out[bh] = m_new;

    // ---- norm update + qn partials (norm_s already resident) ---------------
    if (tid < HEAD) {
        float nn = fmaf(f_g, norm_s[tid], i_g * k_s[tid]);
        if (norm_out) norm_out[(size_t)bh * HEAD + tid] = nn;
        float qn = q_s[tid] * nn;
        #pragma unroll
        for (int off = 16; off > 0; off >>= 1)
            qn += __shfl_xor_sync(0xffffffffu, qn, off);
        if (lane == 0) pq[warp] = qn;
    }

    // ---- main stream: rolling depth-8 pipeline over 16 rows -----------------
    float4 vreg = ((const float4*)v_s)[lane];
    float4 num  = make_float4(0.f, 0.f, 0.f, 0.f);

    #pragma unroll
    for (int i = 0; i < 16; ++i) {
        float4 c = cv[i & 7];
        if (i + 8 < 16)
            cv[i & 7] = __ldcs(cp + (i + 8) * 256);   // keep 8 rows in flight
        int r = i * 8 + warp;
        float a = i_g * k_s[r];
        float4 cn;
        cn.x = fmaf(f_g, c.x, a * vreg.x);
        cn.y = fmaf(f_g, c.y, a * vreg.y);
        cn.z = fmaf(f_g, c.z, a * vreg.z);
        cn.w = fmaf(f_g, c.w, a * vreg.w);
        if (op) __stcs(op + i * 256, cn);
        float qr = q_s[r];
        num.x = fmaf(qr, cn.x, num.x);
        num.y = fmaf(qr, cn.y, num.y);
        num.z = fmaf(qr, cn.z, num.z);
        num.w = fmaf(qr, cn.w, num.w);
    }

    // ---- numerator reduction + denominator + GN stats, all in warp 0 --------
    snum[tid] = num;
    __syncthreads();                                   // sync #2 (covers pq)
    if (tid < 32) {
        float4 a = snum[tid];
        #pragma unroll
        for (int j = 1; j < 8; ++j) {
            float4 bb = snum[tid + 32 * j];
            a.x += bb.x; a.y += bb.y; a.z += bb.z; a.w += bb.w;
        }
        float qn    = pq[0] + pq[1] + pq[2] + pq[3];
        float denom = fmaxf(fabsf(qn), expf(-m_new)) + 1e-6f;
        float inv   = 1.f / denom;
        a.x *= inv; a.y *= inv; a.z *= inv; a.w *= inv;
        snum[tid] = a;                 // flattened: o[0..127]
        float so  = a.x + a.y + a.z + a.w;
        float so2 = a.x*a.x + a.y*a.y + a.z*a.z + a.w*a.w;
        #pragma unroll
        for (int off = 16; off > 0; off >>= 1) {
            so  += __shfl_xor_sync(0xffffffffu, so,  off);
            so2 += __shfl_xor_sync(0xffffffffu, so2, off);
        }
        if (lane == 0) {
            float mu  = so * (1.f / HEAD);
            float var = so2 * (1.f / HEAD) - mu * mu;
            s_mu   = mu;
            s_rstd = rsqrtf(var + 1e-5f);
        }
    }
    __syncthreads();                                   // sync #3

    if (tid < HEAD) {
        float o  = ((const float*)snum)[tid];
        int   ch = h * HEAD + tid;
        out[(size_t)b * HIDDEN + ch] = (o - s_mu) * s_rstd * gamma[ch] + beta[ch];
    }
}

// ---------------------------------------------------------------------------
extern "C" void kernel_launch(void* const* d_in, const int* in_sizes, int n_in,
                              void* d_out, int out_size)
{
    const float* q     = (const float*)d_in[0];
    const float* k     = (const float*)d_in[1];
    const float* v     = (const float*)d_in[2];
    const float* cell  = (const float*)d_in[3];
    const float* norm  = (const float*)d_in[4];
    const float* maxs  = (const float*)d_in[5];
    const float* Wi    = (const float*)d_in[6];
    const float* bi    = (const float*)d_in[7];
    const float* Wf    = (const float*)d_in[8];
    const float* bf    = (const float*)d_in[9];
    const float* gamma = (const float*)d_in[10];
    const float* beta  = (const float*)d_in[11];

    float* out = (float*)d_out;

    const size_t OUT_N  = (size_t)BATCH * HIDDEN;                 // 524288
    const size_t CELL_N = (size_t)BATCH * HEADS * HEAD * HEAD;    // 67108864
    const size_t NORM_N = (size_t)BATCH * HEADS * HEAD;           // 524288
    const size_t MAX_N  = (size_t)BATCH * HEADS;                  // 4096

    float* cell_out = 0;
    float* norm_out = 0;
    float* max_out  = 0;
    if ((size_t)out_size >= OUT_N + CELL_N + NORM_N + MAX_N) {
        cell_out = out + OUT_N;
        norm_out = cell_out + CELL_N;
        max_out  = norm_out + NORM_N;
    }

    mlstm_fused_kernel<<<BATCH * HEADS, 256>>>(q, k, v, cell, norm, maxs,
                                               Wi, bi, Wf, bf, gamma, beta,
                                               out, cell_out, norm_out, max_out);
}